// round 4
// baseline (speedup 1.0000x reference)
#include <cuda_runtime.h>
#include <math.h>

#define S_LEN 8192
#define DIM   1024
#define NHEAD 16
#define HDIM  64
#define WIN   512

// Scratch (allocation-free rule: __device__ globals)
static __device__ float g_Q[(size_t)S_LEN * DIM];
static __device__ float g_K[(size_t)S_LEN * DIM];
static __device__ float g_V[(size_t)S_LEN * DIM];
static __device__ float g_O[(size_t)S_LEN * DIM];

// ---------------------------------------------------------------------------
// Generic 128x128 NT GEMM tile: C[rowBase:+128, outColBase:+128] =
//   A[rowBase:+128, :K] * B[wRowBase:+128, :K]^T    (both K-contiguous, K=DIM)
// 256 threads, BK=16, 8x8 per-thread micro-tile split into 2x2 quadrants of 4x4.
// ---------------------------------------------------------------------------
__device__ __forceinline__ void gemm_tile_128(
    const float* __restrict__ A, const float* __restrict__ B, float* __restrict__ C,
    int rowBase, int wRowBase, int outColBase)
{
    __shared__ float As[16][128];
    __shared__ float Bs[16][128];
    const int tid  = threadIdx.x;
    const int tx   = tid & 15;        // 0..15 -> N quadrant offset tx*4
    const int ty   = tid >> 4;        // 0..15 -> M quadrant offset ty*4
    const int lrow = tid >> 2;        // 0..63 loader row
    const int lcol = (tid & 3) << 2;  // 0,4,8,12 loader k-col

    float acc[2][2][4][4];
#pragma unroll
    for (int a = 0; a < 2; a++)
#pragma unroll
        for (int b = 0; b < 2; b++)
#pragma unroll
            for (int i = 0; i < 4; i++)
#pragma unroll
                for (int j = 0; j < 4; j++) acc[a][b][i][j] = 0.f;

    const float* Ap = A + (size_t)(rowBase + lrow) * DIM + lcol;
    const float* Bp = B + (size_t)(wRowBase + lrow) * DIM + lcol;

    for (int k0 = 0; k0 < DIM; k0 += 16) {
#pragma unroll
        for (int r = 0; r < 2; r++) {
            float4 va = *(const float4*)(Ap + (size_t)r * 64 * DIM + k0);
            As[lcol + 0][lrow + r * 64] = va.x;
            As[lcol + 1][lrow + r * 64] = va.y;
            As[lcol + 2][lrow + r * 64] = va.z;
            As[lcol + 3][lrow + r * 64] = va.w;
            float4 vb = *(const float4*)(Bp + (size_t)r * 64 * DIM + k0);
            Bs[lcol + 0][lrow + r * 64] = vb.x;
            Bs[lcol + 1][lrow + r * 64] = vb.y;
            Bs[lcol + 2][lrow + r * 64] = vb.z;
            Bs[lcol + 3][lrow + r * 64] = vb.w;
        }
        __syncthreads();
#pragma unroll
        for (int kk = 0; kk < 16; kk++) {
            float4 a0 = *(const float4*)&As[kk][ty * 4];
            float4 a1 = *(const float4*)&As[kk][ty * 4 + 64];
            float4 b0 = *(const float4*)&Bs[kk][tx * 4];
            float4 b1 = *(const float4*)&Bs[kk][tx * 4 + 64];
            float ar[2][4] = {{a0.x, a0.y, a0.z, a0.w}, {a1.x, a1.y, a1.z, a1.w}};
            float br[2][4] = {{b0.x, b0.y, b0.z, b0.w}, {b1.x, b1.y, b1.z, b1.w}};
#pragma unroll
            for (int ih = 0; ih < 2; ih++)
#pragma unroll
                for (int jh = 0; jh < 2; jh++)
#pragma unroll
                    for (int i = 0; i < 4; i++)
#pragma unroll
                        for (int j = 0; j < 4; j++)
                            acc[ih][jh][i][j] += ar[ih][i] * br[jh][j];
        }
        __syncthreads();
    }

#pragma unroll
    for (int ih = 0; ih < 2; ih++) {
#pragma unroll
        for (int i = 0; i < 4; i++) {
            int row = rowBase + ih * 64 + ty * 4 + i;
#pragma unroll
            for (int jh = 0; jh < 2; jh++) {
                float4 v = make_float4(acc[ih][jh][i][0], acc[ih][jh][i][1],
                                       acc[ih][jh][i][2], acc[ih][jh][i][3]);
                *(float4*)&C[(size_t)row * DIM + outColBase + jh * 64 + tx * 4] = v;
            }
        }
    }
}

// ---------------------------------------------------------------------------
// Fused QKV projection: grid.y 0..23 -> 8 tiles each of Q, K, V
// ---------------------------------------------------------------------------
__global__ void __launch_bounds__(256) qkv_gemm_kernel(
    const float* __restrict__ x,
    const float* __restrict__ Wq,
    const float* __restrict__ Wk,
    const float* __restrict__ Wv)
{
    int sel = blockIdx.y >> 3;
    const float* B = (sel == 0) ? Wq : (sel == 1) ? Wk : Wv;
    float* C = (sel == 0) ? g_Q : (sel == 1) ? g_K : g_V;
    int cb = (blockIdx.y & 7) * 128;
    gemm_tile_128(x, B, C, blockIdx.x * 128, cb, cb);
}

__global__ void __launch_bounds__(256) out_gemm_kernel(
    const float* __restrict__ Wo, float* __restrict__ out)
{
    gemm_tile_128(g_O, Wo, out, blockIdx.x * 128, blockIdx.y * 128, blockIdx.y * 128);
}

// ---------------------------------------------------------------------------
// RoPE, interleaved-pair convention. EXACTLY one thread per (seq, pair):
// total pairs = S_LEN * DIM/2 = 4,194,304 -> grid.x = that / 256 = 16384.
// (R2 bug: grid was halved, leaving s >= 4096 un-rotated -> rel_err 0.637.)
// blockIdx.y: 0 -> Q, 1 -> K.
// ---------------------------------------------------------------------------
__global__ void __launch_bounds__(256) rope_kernel()
{
    float* buf = (blockIdx.y == 0) ? g_Q : g_K;
    int idx = blockIdx.x * blockDim.x + threadIdx.x; // 0 .. S*512-1
    int s = idx >> 9;       // sequence position
    int p = idx & 511;      // pair index within row of 1024
    int i = p & 31;         // pair index within head (D/2 = 32)
    float e    = (float)(2 * i) * (1.0f / (float)HDIM);
    float invf = powf(10000.0f, -e);          // accurate powf: phase error matters at s~8k
    float ang  = (float)s * invf;
    float sn, cs;
    sincosf(ang, &sn, &cs);
    float2* ptr = (float2*)(buf + (size_t)s * DIM) + p;
    float2 v = *ptr;
    float x1 = v.x, x2 = v.y;
    v.x = x1 * cs - x2 * sn;
    v.y = x1 * sn + x2 * cs;
    *ptr = v;
}

// ---------------------------------------------------------------------------
// Sliding-window causal attention, flash-style online softmax.
// Block = (head, 64-query tile), 256 threads. Key tiles of 64 over
// [max(0, qbase-511) aligned down, qbase]. Mask: q-511 <= k <= q.
// ---------------------------------------------------------------------------
__device__ __forceinline__ float rmax16(float v) {
#pragma unroll
    for (int o = 1; o < 16; o <<= 1) v = fmaxf(v, __shfl_xor_sync(0xffffffffu, v, o));
    return v;
}
__device__ __forceinline__ float rsum16(float v) {
#pragma unroll
    for (int o = 1; o < 16; o <<= 1) v += __shfl_xor_sync(0xffffffffu, v, o);
    return v;
}

__global__ void __launch_bounds__(256) attn_kernel()
{
    __shared__ float Qt[64][64];   // Qt[d][q], pre-scaled by 1/8
    __shared__ float KPt[64][64];  // K phase: [d][k] ; P phase: [k][q]
    __shared__ float Vs[64][64];   // [k][d]

    const int h     = blockIdx.y;
    const int qbase = blockIdx.x * 64;
    const int tid   = threadIdx.x;
    const int tx    = tid & 15;
    const int ty    = tid >> 4;
    const int lrow  = tid >> 2;        // 0..63
    const int lc16  = (tid & 3) << 4;  // 0,16,32,48

    // Load Q tile transposed, fold in softmax scale 1/sqrt(64)
    {
        const float* qp = g_Q + (size_t)(qbase + lrow) * DIM + h * HDIM + lc16;
#pragma unroll
        for (int c = 0; c < 16; c += 4) {
            float4 v = *(const float4*)(qp + c);
            Qt[lc16 + c + 0][lrow] = v.x * 0.125f;
            Qt[lc16 + c + 1][lrow] = v.y * 0.125f;
            Qt[lc16 + c + 2][lrow] = v.z * 0.125f;
            Qt[lc16 + c + 3][lrow] = v.w * 0.125f;
        }
    }

    float o[4][4];
    float m[4], l[4];
#pragma unroll
    for (int i = 0; i < 4; i++) {
        m[i] = -1e30f; l[i] = 0.f;
#pragma unroll
        for (int j = 0; j < 4; j++) o[i][j] = 0.f;
    }

    int k0 = qbase - (WIN - 1);
    if (k0 < 0) k0 = 0;
    k0 &= ~63;
    __syncthreads();

    for (int kb = k0; kb <= qbase; kb += 64) {
        // Load K (transposed) and V (natural)
        const float* kp = g_K + (size_t)(kb + lrow) * DIM + h * HDIM + lc16;
        const float* vp = g_V + (size_t)(kb + lrow) * DIM + h * HDIM + lc16;
#pragma unroll
        for (int c = 0; c < 16; c += 4) {
            float4 kv = *(const float4*)(kp + c);
            KPt[lc16 + c + 0][lrow] = kv.x;
            KPt[lc16 + c + 1][lrow] = kv.y;
            KPt[lc16 + c + 2][lrow] = kv.z;
            KPt[lc16 + c + 3][lrow] = kv.w;
            float4 vv = *(const float4*)(vp + c);
            *(float4*)&Vs[lrow][lc16 + c] = vv;
        }
        __syncthreads();

        // S = Q K^T (pre-scaled)
        float s[4][4];
#pragma unroll
        for (int i = 0; i < 4; i++)
#pragma unroll
            for (int j = 0; j < 4; j++) s[i][j] = 0.f;
#pragma unroll 8
        for (int kk = 0; kk < 64; kk++) {
            float4 qv = *(const float4*)&Qt[kk][ty * 4];
            float4 kv = *(const float4*)&KPt[kk][tx * 4];
            float qa[4] = {qv.x, qv.y, qv.z, qv.w};
            float ka[4] = {kv.x, kv.y, kv.z, kv.w};
#pragma unroll
            for (int i = 0; i < 4; i++)
#pragma unroll
                for (int j = 0; j < 4; j++) s[i][j] += qa[i] * ka[j];
        }

        // Mask + online softmax update (per query row)
#pragma unroll
        for (int i = 0; i < 4; i++) {
            int q = qbase + ty * 4 + i;
            float mx = -1e30f;
#pragma unroll
            for (int j = 0; j < 4; j++) {
                int k = kb + tx * 4 + j;
                if (k > q || k < q - (WIN - 1)) s[i][j] = -1e30f;
                mx = fmaxf(mx, s[i][j]);
            }
            mx = rmax16(mx);
            float mnew = fmaxf(m[i], mx);
            float alpha, rs = 0.f;
            if (mnew > -1e29f) {
                alpha = __expf(m[i] - mnew);  // -> 0 when m[i] still -1e30
#pragma unroll
                for (int j = 0; j < 4; j++) {
                    float p = __expf(s[i][j] - mnew);  // masked -1e30 -> 0
                    s[i][j] = p;
                    rs += p;
                }
            } else {
                // nothing valid for this row yet in this tile
                alpha = 1.f;
#pragma unroll
                for (int j = 0; j < 4; j++) s[i][j] = 0.f;
            }
            rs = rsum16(rs);
            l[i] = l[i] * alpha + rs;
#pragma unroll
            for (int j = 0; j < 4; j++) o[i][j] *= alpha;
            m[i] = mnew;
        }
        __syncthreads();  // all KPt (K-phase) reads done before P^T overwrite

        // Store P^T into KPt: KPt[k][q]
#pragma unroll
        for (int i = 0; i < 4; i++)
#pragma unroll
            for (int j = 0; j < 4; j++)
                KPt[tx * 4 + j][ty * 4 + i] = s[i][j];
        __syncthreads();

        // O += P V
#pragma unroll 8
        for (int kk = 0; kk < 64; kk++) {
            float4 pv = *(const float4*)&KPt[kk][ty * 4];
            float4 vv = *(const float4*)&Vs[kk][tx * 4];
            float pa[4] = {pv.x, pv.y, pv.z, pv.w};
            float va[4] = {vv.x, vv.y, vv.z, vv.w};
#pragma unroll
            for (int i = 0; i < 4; i++)
#pragma unroll
                for (int j = 0; j < 4; j++) o[i][j] += pa[i] * va[j];
        }
        __syncthreads();  // before next tile overwrites KPt / Vs
    }

    // Normalize and write O
#pragma unroll
    for (int i = 0; i < 4; i++) {
        float inv = 1.0f / l[i];
        float4 v = make_float4(o[i][0] * inv, o[i][1] * inv, o[i][2] * inv, o[i][3] * inv);
        *(float4*)&g_O[(size_t)(qbase + ty * 4 + i) * DIM + h * HDIM + tx * 4] = v;
    }
}

// ---------------------------------------------------------------------------
extern "C" void kernel_launch(void* const* d_in, const int* in_sizes, int n_in,
                              void* d_out, int out_size)
{
    const float* x  = (const float*)d_in[0];
    const float* Wq = (const float*)d_in[1];
    const float* Wk = (const float*)d_in[2];
    const float* Wv = (const float*)d_in[3];
    const float* Wo = (const float*)d_in[4];
    // d_in[5] = window_size (shape-specialized to 512)
    float* out = (float*)d_out;

    qkv_gemm_kernel<<<dim3(S_LEN / 128, 24), 256>>>(x, Wq, Wk, Wv);
    // One thread per (seq, pair): S*DIM/2 = 4194304 threads -> 16384 blocks of 256.
    rope_kernel<<<dim3((S_LEN * (DIM / 2)) / 256, 2), 256>>>();
    attn_kernel<<<dim3(S_LEN / 64, NHEAD), 256>>>();
    out_gemm_kernel<<<dim3(S_LEN / 128, 8), 256>>>(Wo, out);
}

// round 6
// speedup vs baseline: 1.4664x; 1.4664x over previous
#include <cuda_runtime.h>
#include <cuda_bf16.h>
#include <math.h>
#include <stdint.h>

#define S_LEN 8192
#define DIM   1024
#define NHEAD 16
#define HDIM  64
#define WIN   512

// Scratch (allocation-free rule: __device__ globals)
static __device__ float g_Q[(size_t)S_LEN * DIM];
static __device__ float g_K[(size_t)S_LEN * DIM];
static __device__ float g_V[(size_t)S_LEN * DIM];
static __device__ float g_O[(size_t)S_LEN * DIM];

// ===========================================================================
// bf16x3 split helpers
// ===========================================================================
__device__ __forceinline__ void split2(float x, float y, uint32_t& h, uint32_t& l)
{
    __nv_bfloat16 hx = __float2bfloat16_rn(x);
    __nv_bfloat16 hy = __float2bfloat16_rn(y);
    float rx = x - __bfloat162float(hx);
    float ry = y - __bfloat162float(hy);
    __nv_bfloat16 lx = __float2bfloat16_rn(rx);
    __nv_bfloat16 ly = __float2bfloat16_rn(ry);
    h = (uint32_t)__bfloat16_as_ushort(hx) | ((uint32_t)__bfloat16_as_ushort(hy) << 16);
    l = (uint32_t)__bfloat16_as_ushort(lx) | ((uint32_t)__bfloat16_as_ushort(ly) << 16);
}

// mma.sync m16n8k16 row.col f32.bf16.bf16.f32 (sm_80+, legal on sm_100 target)
__device__ __forceinline__ void mma16816(float* c, const uint32_t* a, const uint32_t* b)
{
    asm volatile(
        "mma.sync.aligned.m16n8k16.row.col.f32.bf16.bf16.f32 "
        "{%0,%1,%2,%3}, {%4,%5,%6,%7}, {%8,%9}, {%0,%1,%2,%3};"
        : "+f"(c[0]), "+f"(c[1]), "+f"(c[2]), "+f"(c[3])
        : "r"(a[0]), "r"(a[1]), "r"(a[2]), "r"(a[3]), "r"(b[0]), "r"(b[1]));
}

// Swizzled smem access: tile rows are 64B (32 bf16); 8 chunks of 8B per row,
// chunk index XORed with (row & 7). Conflict-free for both the fragment LDS.32
// pattern (banks fully distinct across a warp) and the 8B STS stores (<=2-way).
__device__ __forceinline__ uint32_t lds32sw(const char* base, int row, int kbyte)
{
    int chunk = kbyte >> 3;
    int w     = kbyte & 7;
    return *(const uint32_t*)(base + row * 64 + ((chunk ^ (row & 7)) << 3) + w);
}
__device__ __forceinline__ uint32_t sts_off(int row, int c4)
{
    return (uint32_t)(row * 64 + ((c4 ^ (row & 7)) << 3));
}

// ===========================================================================
// bf16x3 NT GEMM: C[mBase:+128, nBase:+128] = A[128,K] * B[128,K]^T, K=1024.
// 256 threads = 8 warps (2 x 4), warp tile 64x32. BK=32, 2-stage double buffer.
// Stage layout: A_hi(8K) A_lo(8K) B_hi(8K) B_lo(8K) = 32KB; 2 stages = 64KB.
// ===========================================================================
#define STAGE_B 32768
#define GEMM_SMEM (2 * STAGE_B)

__device__ __forceinline__ void gemm_bf16x3(const float* __restrict__ A,
                                            const float* __restrict__ B,
                                            float* __restrict__ C,
                                            int mBase, int nBase)
{
    extern __shared__ char smx[];
    const int tid  = threadIdx.x;
    const int warp = tid >> 5;
    const int lane = tid & 31;
    const int g    = lane >> 2;   // groupID 0..7
    const int tig  = lane & 3;    // thread-in-group 0..3
    const int wm   = (warp >> 2) * 64;  // warp row offset (0, 64)
    const int wn   = (warp & 3) * 32;   // warp col offset (0..96)

    const int rowb = tid >> 3;    // loader row base 0..31
    const int c4   = tid & 7;     // loader float4 column 0..7

    const float* Ap = A + (size_t)(mBase + rowb) * DIM + c4 * 4;
    const float* Bp = B + (size_t)(nBase + rowb) * DIM + c4 * 4;

    float acc[4][4][4];
#pragma unroll
    for (int mi = 0; mi < 4; mi++)
#pragma unroll
        for (int ni = 0; ni < 4; ni++)
#pragma unroll
            for (int r = 0; r < 4; r++) acc[mi][ni][r] = 0.f;

    float4 aS[4], bS[4];
    // prefetch k-chunk 0
#pragma unroll
    for (int i = 0; i < 4; i++) {
        aS[i] = *(const float4*)(Ap + (size_t)i * 32 * DIM);
        bS[i] = *(const float4*)(Bp + (size_t)i * 32 * DIM);
    }

    const uint32_t soff = sts_off(0, 0); (void)soff;

    // initial STS into stage 0
    {
        char* Ah = smx;            char* Al = smx + 8192;
        char* Bh = smx + 16384;    char* Bl = smx + 24576;
#pragma unroll
        for (int i = 0; i < 4; i++) {
            int row = rowb + 32 * i;
            uint32_t o = sts_off(row, c4);
            uint32_t h01, l01, h23, l23;
            split2(aS[i].x, aS[i].y, h01, l01);
            split2(aS[i].z, aS[i].w, h23, l23);
            *(uint2*)(Ah + o) = make_uint2(h01, h23);
            *(uint2*)(Al + o) = make_uint2(l01, l23);
            split2(bS[i].x, bS[i].y, h01, l01);
            split2(bS[i].z, bS[i].w, h23, l23);
            *(uint2*)(Bh + o) = make_uint2(h01, h23);
            *(uint2*)(Bl + o) = make_uint2(l01, l23);
        }
    }
    __syncthreads();

#pragma unroll 1
    for (int it = 0; it < 32; ++it) {
        // prefetch next k-chunk into regs (hides gmem latency under mma)
        if (it < 31) {
            const float* Ap2 = Ap + (it + 1) * 32;
            const float* Bp2 = Bp + (it + 1) * 32;
#pragma unroll
            for (int i = 0; i < 4; i++) {
                aS[i] = *(const float4*)(Ap2 + (size_t)i * 32 * DIM);
                bS[i] = *(const float4*)(Bp2 + (size_t)i * 32 * DIM);
            }
        }

        // compute from stage it&1
        const char* st = smx + (it & 1) * STAGE_B;
        const char* Ah = st;         const char* Al = st + 8192;
        const char* Bh = st + 16384; const char* Bl = st + 24576;

#pragma unroll
        for (int ks = 0; ks < 2; ++ks) {
            const int kb = ks * 32;  // byte offset of k16-step within 64B row
            uint32_t bh[4][2], bl[4][2];
#pragma unroll
            for (int ni = 0; ni < 4; ni++) {
                int n = wn + ni * 8 + g;
                bh[ni][0] = lds32sw(Bh, n, kb + tig * 4);
                bh[ni][1] = lds32sw(Bh, n, kb + tig * 4 + 16);
                bl[ni][0] = lds32sw(Bl, n, kb + tig * 4);
                bl[ni][1] = lds32sw(Bl, n, kb + tig * 4 + 16);
            }
#pragma unroll
            for (int mi = 0; mi < 4; mi++) {
                int m = wm + mi * 16 + g;
                uint32_t ah[4], al[4];
                ah[0] = lds32sw(Ah, m,     kb + tig * 4);
                ah[1] = lds32sw(Ah, m + 8, kb + tig * 4);
                ah[2] = lds32sw(Ah, m,     kb + tig * 4 + 16);
                ah[3] = lds32sw(Ah, m + 8, kb + tig * 4 + 16);
                al[0] = lds32sw(Al, m,     kb + tig * 4);
                al[1] = lds32sw(Al, m + 8, kb + tig * 4);
                al[2] = lds32sw(Al, m,     kb + tig * 4 + 16);
                al[3] = lds32sw(Al, m + 8, kb + tig * 4 + 16);
#pragma unroll
                for (int ni = 0; ni < 4; ni++) {
                    mma16816(acc[mi][ni], ah, bh[ni]);  // hi*hi
                    mma16816(acc[mi][ni], al, bh[ni]);  // lo*hi
                    mma16816(acc[mi][ni], ah, bl[ni]);  // hi*lo
                }
            }
        }

        // store next k-chunk into the other stage, then sync
        if (it < 31) {
            char* st2 = smx + ((it + 1) & 1) * STAGE_B;
            char* Ah2 = st2;         char* Al2 = st2 + 8192;
            char* Bh2 = st2 + 16384; char* Bl2 = st2 + 24576;
#pragma unroll
            for (int i = 0; i < 4; i++) {
                int row = rowb + 32 * i;
                uint32_t o = sts_off(row, c4);
                uint32_t h01, l01, h23, l23;
                split2(aS[i].x, aS[i].y, h01, l01);
                split2(aS[i].z, aS[i].w, h23, l23);
                *(uint2*)(Ah2 + o) = make_uint2(h01, h23);
                *(uint2*)(Al2 + o) = make_uint2(l01, l23);
                split2(bS[i].x, bS[i].y, h01, l01);
                split2(bS[i].z, bS[i].w, h23, l23);
                *(uint2*)(Bh2 + o) = make_uint2(h01, h23);
                *(uint2*)(Bl2 + o) = make_uint2(l01, l23);
            }
            __syncthreads();
        }
    }

    // Epilogue: fragment C mapping c0=C[g][tig*2], c1=+1col, c2=row+8, c3=+1col
#pragma unroll
    for (int mi = 0; mi < 4; mi++) {
#pragma unroll
        for (int ni = 0; ni < 4; ni++) {
            int r = mBase + wm + mi * 16 + g;
            int c = nBase + wn + ni * 8 + tig * 2;
            float* p = C + (size_t)r * DIM + c;
            *(float2*)p = make_float2(acc[mi][ni][0], acc[mi][ni][1]);
            *(float2*)(p + (size_t)8 * DIM) = make_float2(acc[mi][ni][2], acc[mi][ni][3]);
        }
    }
}

// grid (24, 64): bx = sel*8 + colTile (bx fastest -> A panel L2 reuse)
__global__ void __launch_bounds__(256) qkv_mma_kernel(
    const float* __restrict__ x, const float* __restrict__ Wq,
    const float* __restrict__ Wk, const float* __restrict__ Wv)
{
    int sel = blockIdx.x >> 3;
    const float* W = (sel == 0) ? Wq : (sel == 1) ? Wk : Wv;
    float* C = (sel == 0) ? g_Q : (sel == 1) ? g_K : g_V;
    gemm_bf16x3(x, W, C, blockIdx.y * 128, (blockIdx.x & 7) * 128);
}

// grid (8, 64)
__global__ void __launch_bounds__(256) out_mma_kernel(
    const float* __restrict__ Wo, float* __restrict__ out)
{
    gemm_bf16x3(g_O, Wo, out, blockIdx.y * 128, blockIdx.x * 128);
}

// ===========================================================================
// RoPE (unchanged, known-correct): one thread per (seq, pair)
// ===========================================================================
__global__ void __launch_bounds__(256) rope_kernel()
{
    float* buf = (blockIdx.y == 0) ? g_Q : g_K;
    int idx = blockIdx.x * blockDim.x + threadIdx.x;
    int s = idx >> 9;
    int p = idx & 511;
    int i = p & 31;
    float e    = (float)(2 * i) * (1.0f / (float)HDIM);
    float invf = powf(10000.0f, -e);
    float ang  = (float)s * invf;
    float sn, cs;
    sincosf(ang, &sn, &cs);
    float2* ptr = (float2*)(buf + (size_t)s * DIM) + p;
    float2 v = *ptr;
    float x1 = v.x, x2 = v.y;
    v.x = x1 * cs - x2 * sn;
    v.y = x1 * sn + x2 * cs;
    *ptr = v;
}

// ===========================================================================
// Sliding-window attention (unchanged, known-correct fp32 flash-style)
// ===========================================================================
__device__ __forceinline__ float rmax16(float v) {
#pragma unroll
    for (int o = 1; o < 16; o <<= 1) v = fmaxf(v, __shfl_xor_sync(0xffffffffu, v, o));
    return v;
}
__device__ __forceinline__ float rsum16(float v) {
#pragma unroll
    for (int o = 1; o < 16; o <<= 1) v += __shfl_xor_sync(0xffffffffu, v, o);
    return v;
}

__global__ void __launch_bounds__(256) attn_kernel()
{
    __shared__ float Qt[64][64];
    __shared__ float KPt[64][64];
    __shared__ float Vs[64][64];

    const int h     = blockIdx.y;
    const int qbase = blockIdx.x * 64;
    const int tid   = threadIdx.x;
    const int tx    = tid & 15;
    const int ty    = tid >> 4;
    const int lrow  = tid >> 2;
    const int lc16  = (tid & 3) << 4;

    {
        const float* qp = g_Q + (size_t)(qbase + lrow) * DIM + h * HDIM + lc16;
#pragma unroll
        for (int c = 0; c < 16; c += 4) {
            float4 v = *(const float4*)(qp + c);
            Qt[lc16 + c + 0][lrow] = v.x * 0.125f;
            Qt[lc16 + c + 1][lrow] = v.y * 0.125f;
            Qt[lc16 + c + 2][lrow] = v.z * 0.125f;
            Qt[lc16 + c + 3][lrow] = v.w * 0.125f;
        }
    }

    float o[4][4];
    float m[4], l[4];
#pragma unroll
    for (int i = 0; i < 4; i++) {
        m[i] = -1e30f; l[i] = 0.f;
#pragma unroll
        for (int j = 0; j < 4; j++) o[i][j] = 0.f;
    }

    int k0 = qbase - (WIN - 1);
    if (k0 < 0) k0 = 0;
    k0 &= ~63;
    __syncthreads();

    for (int kb = k0; kb <= qbase; kb += 64) {
        const float* kp = g_K + (size_t)(kb + lrow) * DIM + h * HDIM + lc16;
        const float* vp = g_V + (size_t)(kb + lrow) * DIM + h * HDIM + lc16;
#pragma unroll
        for (int c = 0; c < 16; c += 4) {
            float4 kv = *(const float4*)(kp + c);
            KPt[lc16 + c + 0][lrow] = kv.x;
            KPt[lc16 + c + 1][lrow] = kv.y;
            KPt[lc16 + c + 2][lrow] = kv.z;
            KPt[lc16 + c + 3][lrow] = kv.w;
            float4 vv = *(const float4*)(vp + c);
            *(float4*)&Vs[lrow][lc16 + c] = vv;
        }
        __syncthreads();

        float s[4][4];
#pragma unroll
        for (int i = 0; i < 4; i++)
#pragma unroll
            for (int j = 0; j < 4; j++) s[i][j] = 0.f;
#pragma unroll 8
        for (int kk = 0; kk < 64; kk++) {
            float4 qv = *(const float4*)&Qt[kk][ty * 4];
            float4 kv = *(const float4*)&KPt[kk][tx * 4];
            float qa[4] = {qv.x, qv.y, qv.z, qv.w};
            float ka[4] = {kv.x, kv.y, kv.z, kv.w};
#pragma unroll
            for (int i = 0; i < 4; i++)
#pragma unroll
                for (int j = 0; j < 4; j++) s[i][j] += qa[i] * ka[j];
        }

#pragma unroll
        for (int i = 0; i < 4; i++) {
            int q = qbase + ty * 4 + i;
            float mx = -1e30f;
#pragma unroll
            for (int j = 0; j < 4; j++) {
                int k = kb + tx * 4 + j;
                if (k > q || k < q - (WIN - 1)) s[i][j] = -1e30f;
                mx = fmaxf(mx, s[i][j]);
            }
            mx = rmax16(mx);
            float mnew = fmaxf(m[i], mx);
            float alpha, rs = 0.f;
            if (mnew > -1e29f) {
                alpha = __expf(m[i] - mnew);
#pragma unroll
                for (int j = 0; j < 4; j++) {
                    float p = __expf(s[i][j] - mnew);
                    s[i][j] = p;
                    rs += p;
                }
            } else {
                alpha = 1.f;
#pragma unroll
                for (int j = 0; j < 4; j++) s[i][j] = 0.f;
            }
            rs = rsum16(rs);
            l[i] = l[i] * alpha + rs;
#pragma unroll
            for (int j = 0; j < 4; j++) o[i][j] *= alpha;
            m[i] = mnew;
        }
        __syncthreads();

#pragma unroll
        for (int i = 0; i < 4; i++)
#pragma unroll
            for (int j = 0; j < 4; j++)
                KPt[tx * 4 + j][ty * 4 + i] = s[i][j];
        __syncthreads();

#pragma unroll 8
        for (int kk = 0; kk < 64; kk++) {
            float4 pv = *(const float4*)&KPt[kk][ty * 4];
            float4 vv = *(const float4*)&Vs[kk][tx * 4];
            float pa[4] = {pv.x, pv.y, pv.z, pv.w};
            float va[4] = {vv.x, vv.y, vv.z, vv.w};
#pragma unroll
            for (int i = 0; i < 4; i++)
#pragma unroll
                for (int j = 0; j < 4; j++) o[i][j] += pa[i] * va[j];
        }
        __syncthreads();
    }

#pragma unroll
    for (int i = 0; i < 4; i++) {
        float inv = 1.0f / l[i];
        float4 v = make_float4(o[i][0] * inv, o[i][1] * inv, o[i][2] * inv, o[i][3] * inv);
        *(float4*)&g_O[(size_t)(qbase + ty * 4 + i) * DIM + h * HDIM + tx * 4] = v;
    }
}

// ---------------------------------------------------------------------------
extern "C" void kernel_launch(void* const* d_in, const int* in_sizes, int n_in,
                              void* d_out, int out_size)
{
    const float* x  = (const float*)d_in[0];
    const float* Wq = (const float*)d_in[1];
    const float* Wk = (const float*)d_in[2];
    const float* Wv = (const float*)d_in[3];
    const float* Wo = (const float*)d_in[4];
    float* out = (float*)d_out;

    cudaFuncSetAttribute(qkv_mma_kernel, cudaFuncAttributeMaxDynamicSharedMemorySize, GEMM_SMEM);
    cudaFuncSetAttribute(out_mma_kernel, cudaFuncAttributeMaxDynamicSharedMemorySize, GEMM_SMEM);

    qkv_mma_kernel<<<dim3(24, 64), 256, GEMM_SMEM>>>(x, Wq, Wk, Wv);
    rope_kernel<<<dim3((S_LEN * (DIM / 2)) / 256, 2), 256>>>();
    attn_kernel<<<dim3(S_LEN / 64, NHEAD), 256>>>();
    out_mma_kernel<<<dim3(8, 64), 256, GEMM_SMEM>>>(Wo, out);
}